// round 1
// baseline (speedup 1.0000x reference)
#include <cuda_runtime.h>

// Problem constants (fixed by the reference: B=32, N=512, D=512)
constexpr int Bb = 32;
constexpr int Np = 512;
constexpr int Dd = 512;

// Tiling
#define BM 64
#define BN 64
#define BK 16

// Scratch for XW = X @ W  (B, N, D) fp32 = 33.5 MB. __device__ global (alloc-free rule).
__device__ float g_xw[Bb * Np * Dd];

// ---------------------------------------------------------------------------
// Kernel 1: XW[b] = X[b] (N x D, row-major) @ W (D x D, row-major)
// ---------------------------------------------------------------------------
__global__ __launch_bounds__(256) void gemm_xw_kernel(
    const float* __restrict__ X, const float* __restrict__ W)
{
    const int bz = blockIdx.z;
    const float* A = X + (size_t)bz * Np * Dd;      // (Np x Dd)
    float* C = g_xw + (size_t)bz * Np * Dd;         // (Np x Dd)
    const int m0 = blockIdx.y * BM;
    const int n0 = blockIdx.x * BN;

    __shared__ __align__(16) float As[BK][BM + 4];  // transposed A tile, padded
    __shared__ __align__(16) float Bs[BK][BN];      // W tile (n contiguous)

    const int tid = threadIdx.x;
    const int tx = tid & 15;   // column group (4 cols each)
    const int ty = tid >> 4;   // row group (4 rows each)

    float acc[4][4] = {};

    for (int k0 = 0; k0 < Dd; k0 += BK) {
        // Load A tile (64 x 16): thread -> row m = tid/4, k-quad kq = tid%4
        {
            const int m  = tid >> 2;
            const int kq = tid & 3;
            float4 v = *reinterpret_cast<const float4*>(A + (size_t)(m0 + m) * Dd + k0 + kq * 4);
            As[kq * 4 + 0][m] = v.x;
            As[kq * 4 + 1][m] = v.y;
            As[kq * 4 + 2][m] = v.z;
            As[kq * 4 + 3][m] = v.w;
        }
        // Load W tile (16 x 64): thread -> k = tid/16, n-quad nq = tid%16
        {
            const int k  = tid >> 4;
            const int nq = tid & 15;
            float4 v = *reinterpret_cast<const float4*>(W + (size_t)(k0 + k) * Dd + n0 + nq * 4);
            *reinterpret_cast<float4*>(&Bs[k][nq * 4]) = v;
        }
        __syncthreads();

        #pragma unroll
        for (int k = 0; k < BK; k++) {
            float4 av = *reinterpret_cast<const float4*>(&As[k][ty * 4]);
            float4 bv = *reinterpret_cast<const float4*>(&Bs[k][tx * 4]);
            float ar[4] = {av.x, av.y, av.z, av.w};
            float br[4] = {bv.x, bv.y, bv.z, bv.w};
            #pragma unroll
            for (int i = 0; i < 4; i++)
                #pragma unroll
                for (int j = 0; j < 4; j++)
                    acc[i][j] += ar[i] * br[j];
        }
        __syncthreads();
    }

    #pragma unroll
    for (int i = 0; i < 4; i++) {
        float4 v = make_float4(acc[i][0], acc[i][1], acc[i][2], acc[i][3]);
        *reinterpret_cast<float4*>(C + (size_t)(m0 + ty * 4 + i) * Dd + n0 + tx * 4) = v;
    }
}

// ---------------------------------------------------------------------------
// Kernel 2: S[b] = XW[b] (N x D) @ X[b]^T  (+bias, diag=0)
//   S[i][j] = sum_e XW[i][e] * X[j][e]   — both operands K(e)-contiguous
// ---------------------------------------------------------------------------
__global__ __launch_bounds__(256) void gemm_score_kernel(
    const float* __restrict__ X, const float* __restrict__ bias,
    float* __restrict__ out)
{
    const int bz = blockIdx.z;
    const float* A  = g_xw + (size_t)bz * Np * Dd;  // (Np x Dd)
    const float* Bt = X    + (size_t)bz * Np * Dd;  // accessed as B^T: row j, col e
    float* C = out + (size_t)bz * Np * Np;
    const int m0 = blockIdx.y * BM;
    const int n0 = blockIdx.x * BN;

    __shared__ __align__(16) float As[BK][BM + 4];
    __shared__ __align__(16) float Bs[BK][BN + 4];

    const int tid = threadIdx.x;
    const int tx = tid & 15;
    const int ty = tid >> 4;

    float acc[4][4] = {};

    for (int k0 = 0; k0 < Dd; k0 += BK) {
        // Load A tile transposed (64 rows x 16 k)
        {
            const int m  = tid >> 2;
            const int kq = tid & 3;
            float4 v = *reinterpret_cast<const float4*>(A + (size_t)(m0 + m) * Dd + k0 + kq * 4);
            As[kq * 4 + 0][m] = v.x;
            As[kq * 4 + 1][m] = v.y;
            As[kq * 4 + 2][m] = v.z;
            As[kq * 4 + 3][m] = v.w;
        }
        // Load B^T tile transposed: Bs[k][n] = X[n0+n][k0+k]
        {
            const int n  = tid >> 2;
            const int kq = tid & 3;
            float4 v = *reinterpret_cast<const float4*>(Bt + (size_t)(n0 + n) * Dd + k0 + kq * 4);
            Bs[kq * 4 + 0][n] = v.x;
            Bs[kq * 4 + 1][n] = v.y;
            Bs[kq * 4 + 2][n] = v.z;
            Bs[kq * 4 + 3][n] = v.w;
        }
        __syncthreads();

        #pragma unroll
        for (int k = 0; k < BK; k++) {
            float4 av = *reinterpret_cast<const float4*>(&As[k][ty * 4]);
            float4 bv = *reinterpret_cast<const float4*>(&Bs[k][tx * 4]);
            float ar[4] = {av.x, av.y, av.z, av.w};
            float br[4] = {bv.x, bv.y, bv.z, bv.w};
            #pragma unroll
            for (int i = 0; i < 4; i++)
                #pragma unroll
                for (int j = 0; j < 4; j++)
                    acc[i][j] += ar[i] * br[j];
        }
        __syncthreads();
    }

    const float bval = *bias;
    #pragma unroll
    for (int i = 0; i < 4; i++) {
        const int gi = m0 + ty * 4 + i;
        float4 v;
        float* vp = &v.x;
        #pragma unroll
        for (int j = 0; j < 4; j++) {
            const int gj = n0 + tx * 4 + j;
            vp[j] = (gi == gj) ? 0.0f : (acc[i][j] + bval);
        }
        *reinterpret_cast<float4*>(C + (size_t)gi * Np + n0 + tx * 4) = v;
    }
}

// ---------------------------------------------------------------------------
extern "C" void kernel_launch(void* const* d_in, const int* in_sizes, int n_in,
                              void* d_out, int out_size)
{
    const float* X    = (const float*)d_in[0];  // (32, 512, 512)
    const float* W    = (const float*)d_in[1];  // (512, 512)
    const float* bias = (const float*)d_in[2];  // scalar
    float* out = (float*)d_out;                 // (32, 512, 512)

    dim3 block(256);
    dim3 grid1(Dd / BN, Np / BM, Bb);  // XW: N x D output
    dim3 grid2(Np / BN, Np / BM, Bb);  // S:  N x N output

    gemm_xw_kernel<<<grid1, block>>>(X, W);
    gemm_score_kernel<<<grid2, block>>>(X, bias, out);
}

// round 4
// speedup vs baseline: 4.7726x; 4.7726x over previous
#include <cuda_runtime.h>
#include <cuda_bf16.h>
#include <cstdint>

// Feature gate: tcgen05 only exists when compiling for compute_103a.
#if defined(__CUDA_ARCH__) && defined(__CUDA_ARCH_FEAT_SM103_ALL)
#define HAS_TC 1
#else
#define HAS_TC 0
#endif

constexpr int Bb = 32, Np = 512, Dd = 512;

// ---------------- scratch (__device__ globals; alloc-free rule) -------------
__device__ __align__(16) __nv_bfloat16 g_xhi [(size_t)Bb * Np * Dd];
__device__ __align__(16) __nv_bfloat16 g_xlo [(size_t)Bb * Np * Dd];
__device__ __align__(16) __nv_bfloat16 g_wthi[(size_t)Dd * Dd];
__device__ __align__(16) __nv_bfloat16 g_wtlo[(size_t)Dd * Dd];
__device__ __align__(16) __nv_bfloat16 g_xwhi[(size_t)Bb * Np * Dd];
__device__ __align__(16) __nv_bfloat16 g_xwlo[(size_t)Bb * Np * Dd];

// ---------------- common helpers -------------------------------------------
__device__ __forceinline__ uint32_t smem_u32(const void* p) {
    uint32_t a;
    asm("{ .reg .u64 t; cvta.to.shared.u64 t, %1; cvt.u32.u64 %0, t; }"
        : "=r"(a) : "l"(p));
    return a;
}
__device__ __forceinline__ void cp_async16(uint32_t dst, const void* src) {
    asm volatile("cp.async.cg.shared.global [%0], [%1], 16;"
                 :: "r"(dst), "l"(src));
}
#define CP_COMMIT()  asm volatile("cp.async.commit_group;" ::: "memory")
#define CP_WAIT(n)   asm volatile("cp.async.wait_group %0;" :: "n"(n) : "memory")

// ---------------- conversion kernels ---------------------------------------
__global__ __launch_bounds__(256) void conv_x_kernel(const float4* __restrict__ X) {
    size_t i = (size_t)blockIdx.x * 256 + threadIdx.x;
    float4 v = X[i];
    union { __nv_bfloat16 b[4]; uint2 u; } H, L;
    const float* f = &v.x;
    #pragma unroll
    for (int j = 0; j < 4; j++) {
        __nv_bfloat16 h = __float2bfloat16_rn(f[j]);
        H.b[j] = h;
        L.b[j] = __float2bfloat16_rn(f[j] - __bfloat162float(h));
    }
    reinterpret_cast<uint2*>(g_xhi)[i] = H.u;
    reinterpret_cast<uint2*>(g_xlo)[i] = L.u;
}

__global__ __launch_bounds__(256) void conv_w_kernel(const float* __restrict__ W) {
    __shared__ float t[32][33];
    int tx = threadIdx.x, ty = threadIdx.y;          // 32 x 8
    int bx = blockIdx.x * 32, by = blockIdx.y * 32;  // bx: n-block, by: k-block
    #pragma unroll
    for (int r = 0; r < 4; r++)
        t[ty + r * 8][tx] = W[(size_t)(by + ty + r * 8) * Dd + bx + tx];
    __syncthreads();
    #pragma unroll
    for (int r = 0; r < 4; r++) {
        int n = bx + ty + r * 8, kk = by + tx;
        float v = t[tx][ty + r * 8];                  // = W[kk][n]
        __nv_bfloat16 h = __float2bfloat16_rn(v);
        g_wthi[(size_t)n * Dd + kk] = h;
        g_wtlo[(size_t)n * Dd + kk] = __float2bfloat16_rn(v - __bfloat162float(h));
    }
}

// ===========================================================================
// Path A: tcgen05 (only compiled under compute_103a)
// ===========================================================================
#if HAS_TC
constexpr int TBM = 128, TBN = 128, TBKE = 64;
constexpr int T_KITERS = Dd / TBKE;               // 8
constexpr int T_NSTAGE = 3;
constexpr int T_TILE_BYTES  = TBM * TBKE * 2;     // 16384
constexpr int T_STAGE_BYTES = 4 * T_TILE_BYTES;   // 65536
constexpr int T_OFF_MBAR  = 8;
constexpr int T_OFF_TILES = 1024;

constexpr uint32_t T_IDESC =
    (1u << 4) | (1u << 7) | (1u << 10) | ((TBN / 8) << 17) | ((TBM / 16) << 24);

__device__ __forceinline__ uint32_t elect_one_pred() {
    uint32_t pred;
    asm volatile("{\n\t.reg .pred p;\n\telect.sync _|p, 0xFFFFFFFF;\n\t"
                 "selp.b32 %0, 1, 0, p;\n\t}" : "=r"(pred));
    return pred;
}
#define MBARRIER_INIT(addr, cnt) \
    asm volatile("mbarrier.init.shared.b64 [%0], %1;" :: "r"(addr), "r"(cnt) : "memory")
#define MBAR_WAIT(addr, parity) do {                                          \
    uint32_t _m = (addr), _p = (parity);                                      \
    asm volatile("{\n\t.reg .pred P1;\n\t"                                    \
        "WAIT_LOOP_%=:\n\t"                                                   \
        "mbarrier.try_wait.parity.acquire.cta.shared::cta.b64 P1, [%0], %1, 0x989680;\n\t" \
        "@P1 bra.uni WAIT_DONE_%=;\n\t"                                       \
        "bra.uni WAIT_LOOP_%=;\n\t"                                           \
        "WAIT_DONE_%=:\n\t}" :: "r"(_m), "r"(_p) : "memory");                 \
} while (0)
#define TCGEN05_ALLOC(smem_addr, n) \
    asm volatile("tcgen05.alloc.cta_group::1.sync.aligned.shared::cta.b32 [%0], %1;" \
                 :: "r"(smem_addr), "r"((uint32_t)(n)) : "memory")
#define TCGEN05_DEALLOC(tmem, n) \
    asm volatile("tcgen05.dealloc.cta_group::1.sync.aligned.b32 %0, %1;" \
                 :: "r"(tmem), "r"((uint32_t)(n)))
#define TCGEN05_RELINQ() \
    asm volatile("tcgen05.relinquish_alloc_permit.cta_group::1.sync.aligned;")
#define TCGEN05_COMMIT(mbar) \
    asm volatile("tcgen05.commit.cta_group::1.mbarrier::arrive::one.shared::cluster.b64 [%0];" \
                 :: "r"(mbar) : "memory")
#define TCGEN05_FENCE_AFTER() \
    asm volatile("tcgen05.fence::after_thread_sync;" ::: "memory")
#define TCGEN05_FENCE_BEFORE() \
    asm volatile("tcgen05.fence::before_thread_sync;" ::: "memory")
#define TCGEN05_WAIT_LD() \
    asm volatile("tcgen05.wait::ld.sync.aligned;" ::: "memory")
#define FENCE_ASYNC_SHARED() \
    asm volatile("fence.proxy.async.shared::cta;" ::: "memory")
#define MMA_BF16_SS(dtmem, adesc, bdesc, idesc, enable) do {                  \
    uint32_t _e = (enable); uint32_t _z = 0;                                  \
    asm volatile("{\n\t.reg .pred p;\n\tsetp.ne.u32 p, %5, 0;\n\t"            \
        "tcgen05.mma.cta_group::1.kind::f16 [%0], %1, %2, %3, {%4,%4,%4,%4}, p;\n\t}" \
        :: "r"(dtmem), "l"(adesc), "l"(bdesc), "r"(idesc), "r"(_z), "r"(_e)   \
        : "memory");                                                          \
} while (0)
#define TCGEN05_LD_X32(r, tmem_addr) \
    asm volatile( \
        "tcgen05.ld.sync.aligned.32x32b.x32.b32 " \
        "{%0, %1, %2, %3, %4, %5, %6, %7, %8, %9, %10, %11, %12, %13, %14, %15, " \
        " %16, %17, %18, %19, %20, %21, %22, %23, %24, %25, %26, %27, %28, %29, %30, %31}, [%32];" \
        : "=r"((r)[0]),  "=r"((r)[1]),  "=r"((r)[2]),  "=r"((r)[3]),  \
          "=r"((r)[4]),  "=r"((r)[5]),  "=r"((r)[6]),  "=r"((r)[7]),  \
          "=r"((r)[8]),  "=r"((r)[9]),  "=r"((r)[10]), "=r"((r)[11]), \
          "=r"((r)[12]), "=r"((r)[13]), "=r"((r)[14]), "=r"((r)[15]), \
          "=r"((r)[16]), "=r"((r)[17]), "=r"((r)[18]), "=r"((r)[19]), \
          "=r"((r)[20]), "=r"((r)[21]), "=r"((r)[22]), "=r"((r)[23]), \
          "=r"((r)[24]), "=r"((r)[25]), "=r"((r)[26]), "=r"((r)[27]), \
          "=r"((r)[28]), "=r"((r)[29]), "=r"((r)[30]), "=r"((r)[31]) \
        : "r"(tmem_addr))

static constexpr uint64_t DESC_BASE_SW128 =
    (uint64_t(2) << 61) | (uint64_t(1) << 46) | (uint64_t(64) << 32) | (uint64_t(1) << 16);
__device__ __forceinline__ uint64_t make_desc(uint32_t addr) {
    return DESC_BASE_SW128 | ((uint64_t)(addr >> 4) & 0x3FFF);
}
#endif  // HAS_TC

constexpr int T_SMEM_TOTAL = 1024 + 3 * 65536;   // 197632 (host-side constant)

template <int STAGE>
__global__ void __launch_bounds__(256, 1) gemm_tc(const float* __restrict__ bias,
                                                  float* __restrict__ out) {
#if HAS_TC
    extern __shared__ char smem[];
    uint32_t sb = smem_u32(smem);
    const int tid = threadIdx.x;
    const int wid = tid >> 5, lid = tid & 31;
    const int z  = blockIdx.z;
    const int m0 = blockIdx.y * TBM, n0 = blockIdx.x * TBN;

    const __nv_bfloat16 *Ahi, *Alo, *Bhi, *Blo;
    if (STAGE == 1) {
        Ahi = g_xhi  + (size_t)z * Np * Dd;  Alo = g_xlo  + (size_t)z * Np * Dd;
        Bhi = g_wthi;                        Blo = g_wtlo;
    } else {
        Ahi = g_xwhi + (size_t)z * Np * Dd;  Alo = g_xwlo + (size_t)z * Np * Dd;
        Bhi = g_xhi  + (size_t)z * Np * Dd;  Blo = g_xlo  + (size_t)z * Np * Dd;
    }

    if (tid == 0)
        for (int s = 0; s < T_NSTAGE; s++) MBARRIER_INIT(sb + T_OFF_MBAR + s * 8, 1);
    if (wid == 0) TCGEN05_ALLOC(sb, 128);
    __syncthreads();
    uint32_t tmem;
    asm volatile("ld.shared.b32 %0, [%1];" : "=r"(tmem) : "r"(sb));
    if (wid == 0) TCGEN05_RELINQ();

    auto load_tile = [&](uint32_t tile, const __nv_bfloat16* src, int row0, int k0) {
        const char* gp = reinterpret_cast<const char*>(src);
        #pragma unroll
        for (int i = 0; i < 4; i++) {
            int chunk = tid + i * 256;
            int row = chunk >> 3;
            int c   = (chunk & 7) * 16;
            cp_async16(tile + row * 128 + (c ^ ((row & 7) << 4)),
                       gp + (size_t)(row0 + row) * (Dd * 2) + k0 * 2 + c);
        }
    };
    auto load_iter = [&](int it) {
        uint32_t stg = sb + T_OFF_TILES + (it % T_NSTAGE) * T_STAGE_BYTES;
        int k0 = it * TBKE;
        load_tile(stg,                    Ahi, m0, k0);
        load_tile(stg + T_TILE_BYTES,     Alo, m0, k0);
        load_tile(stg + 2 * T_TILE_BYTES, Bhi, n0, k0);
        load_tile(stg + 3 * T_TILE_BYTES, Blo, n0, k0);
        CP_COMMIT();
    };
    load_iter(0);
    load_iter(1);

    for (int k = 0; k < T_KITERS; k++) {
        if (k == T_KITERS - 1) { CP_WAIT(0); } else { CP_WAIT(1); }
        FENCE_ASYNC_SHARED();
        __syncthreads();

        if (wid == 0) {
            uint32_t stg = sb + T_OFF_TILES + (k % T_NSTAGE) * T_STAGE_BYTES;
            uint64_t dAh = make_desc(stg);
            uint64_t dAl = make_desc(stg + T_TILE_BYTES);
            uint64_t dBh = make_desc(stg + 2 * T_TILE_BYTES);
            uint64_t dBl = make_desc(stg + 3 * T_TILE_BYTES);
            if (elect_one_pred()) {
                #pragma unroll
                for (int s = 0; s < 4; s++) {             // K=16 per MMA
                    uint64_t o = (uint64_t)(s * 2);
                    MMA_BF16_SS(tmem, dAh + o, dBh + o, T_IDESC, (k == 0 && s == 0) ? 0u : 1u);
                    MMA_BF16_SS(tmem, dAh + o, dBl + o, T_IDESC, 1u);
                    MMA_BF16_SS(tmem, dAl + o, dBh + o, T_IDESC, 1u);
                }
                TCGEN05_COMMIT(sb + T_OFF_MBAR + (k % T_NSTAGE) * 8);
            }
        }

        if (k + 2 < T_KITERS) {
            if (k >= 1)
                MBAR_WAIT(sb + T_OFF_MBAR + ((k - 1) % T_NSTAGE) * 8, ((k - 1) / T_NSTAGE) & 1);
            load_iter(k + 2);
        }
    }

    MBAR_WAIT(sb + T_OFF_MBAR + ((T_KITERS - 1) % T_NSTAGE) * 8,
              ((T_KITERS - 1) / T_NSTAGE) & 1);
    TCGEN05_FENCE_AFTER();

    if (wid < 4) {
        const int gi = m0 + wid * 32 + lid;
        if (STAGE == 1) {
            size_t base = ((size_t)z * Np + gi) * Dd + n0;
            #pragma unroll
            for (int c0 = 0; c0 < TBN; c0 += 32) {
                uint32_t r[32];
                TCGEN05_LD_X32(r, tmem + c0);
                TCGEN05_WAIT_LD();
                __align__(16) __nv_bfloat16 hs[32], ls[32];
                #pragma unroll
                for (int c = 0; c < 32; c++) {
                    float v = __uint_as_float(r[c]);
                    __nv_bfloat16 h = __float2bfloat16_rn(v);
                    hs[c] = h;
                    ls[c] = __float2bfloat16_rn(v - __bfloat162float(h));
                }
                uint4* dh = reinterpret_cast<uint4*>(g_xwhi + base + c0);
                uint4* dl = reinterpret_cast<uint4*>(g_xwlo + base + c0);
                const uint4* sh = reinterpret_cast<const uint4*>(hs);
                const uint4* sl = reinterpret_cast<const uint4*>(ls);
                #pragma unroll
                for (int q = 0; q < 4; q++) { dh[q] = sh[q]; dl[q] = sl[q]; }
            }
        } else {
            const float bv = *bias;
            size_t base = ((size_t)z * Np + gi) * Np + n0;
            #pragma unroll
            for (int c0 = 0; c0 < TBN; c0 += 32) {
                uint32_t r[32];
                TCGEN05_LD_X32(r, tmem + c0);
                TCGEN05_WAIT_LD();
                __align__(16) float vs[32];
                #pragma unroll
                for (int c = 0; c < 32; c++) {
                    int gj = n0 + c0 + c;
                    float v = __uint_as_float(r[c]) + bv;
                    vs[c] = (gi == gj) ? 0.0f : v;
                }
                float4* d = reinterpret_cast<float4*>(out + base + c0);
                const float4* s = reinterpret_cast<const float4*>(vs);
                #pragma unroll
                for (int q = 0; q < 8; q++) d[q] = s[q];
            }
        }
        TCGEN05_FENCE_BEFORE();
    }
    __syncthreads();
    if (wid == 0) TCGEN05_DEALLOC(tmem, 128);
#endif  // HAS_TC
}

// ===========================================================================
// Path B: HMMA mma.sync fallback (compiled only when tcgen05 unavailable)
// ===========================================================================
constexpr int H_ROWB       = 80;                  // padded smem row stride (bytes)
constexpr int H_TILE_BYTES = 128 * H_ROWB;        // 10240
constexpr int H_STAGE_BYTES = 4 * H_TILE_BYTES;   // 40960
constexpr int H_NSTAGE = 3;
constexpr int H_SMEM_TOTAL = H_NSTAGE * H_STAGE_BYTES;  // 122880
constexpr int H_KITERS = Dd / 32;                 // 16

#if !HAS_TC
__device__ __forceinline__ void ldsm4(uint32_t* r, uint32_t addr) {
    asm volatile("ldmatrix.sync.aligned.m8n8.x4.shared.b16 {%0,%1,%2,%3}, [%4];"
                 : "=r"(r[0]), "=r"(r[1]), "=r"(r[2]), "=r"(r[3]) : "r"(addr));
}
__device__ __forceinline__ void mma_bf16(float* d, const uint32_t* a, const uint32_t* b) {
    asm volatile(
        "mma.sync.aligned.m16n8k16.row.col.f32.bf16.bf16.f32 "
        "{%0,%1,%2,%3},{%4,%5,%6,%7},{%8,%9},{%0,%1,%2,%3};"
        : "+f"(d[0]), "+f"(d[1]), "+f"(d[2]), "+f"(d[3])
        : "r"(a[0]), "r"(a[1]), "r"(a[2]), "r"(a[3]), "r"(b[0]), "r"(b[1]));
}
#endif

template <int STAGE>
__global__ void __launch_bounds__(256, 1) gemm_hmma(const float* __restrict__ bias,
                                                    float* __restrict__ out) {
#if !HAS_TC
    extern __shared__ char smem[];
    uint32_t sb = smem_u32(smem);
    const int tid = threadIdx.x, lane = tid & 31, w = tid >> 5;
    const int wm = w & 1, wn = w >> 1;           // warp tile: 64 x 32
    const int z  = blockIdx.z;
    const int m0 = blockIdx.y * 128, n0 = blockIdx.x * 128;

    const __nv_bfloat16 *Ahi, *Alo, *Bhi, *Blo;
    if (STAGE == 1) {
        Ahi = g_xhi  + (size_t)z * Np * Dd;  Alo = g_xlo  + (size_t)z * Np * Dd;
        Bhi = g_wthi;                        Blo = g_wtlo;
    } else {
        Ahi = g_xwhi + (size_t)z * Np * Dd;  Alo = g_xwlo + (size_t)z * Np * Dd;
        Bhi = g_xhi  + (size_t)z * Np * Dd;  Blo = g_xlo  + (size_t)z * Np * Dd;
    }

    float acc[4][4][4] = {};   // [mtile][ntile][reg]

    const __nv_bfloat16* srcs[4] = {Ahi, Alo, Bhi, Blo};
    const int r0s[4] = {m0, m0, n0, n0};

    auto load_stage = [&](int kt) {
        uint32_t st = sb + (kt % H_NSTAGE) * H_STAGE_BYTES;
        int k0 = kt * 32;
        #pragma unroll
        for (int t = 0; t < 4; t++) {
            const char* gp = reinterpret_cast<const char*>(srcs[t] + (size_t)r0s[t] * Dd + k0);
            uint32_t tb = st + t * H_TILE_BYTES;
            #pragma unroll
            for (int i = 0; i < 2; i++) {
                int chunk = tid * 2 + i;
                int row = chunk >> 2, c = chunk & 3;
                cp_async16(tb + row * H_ROWB + c * 16, gp + (size_t)row * (Dd * 2) + c * 16);
            }
        }
        CP_COMMIT();
    };

    load_stage(0);
    load_stage(1);

    for (int kt = 0; kt < H_KITERS; kt++) {
        if (kt < H_KITERS - 2) { CP_WAIT(1); } else { CP_WAIT(0); }
        __syncthreads();
        if (kt + 2 < H_KITERS) load_stage(kt + 2);

        uint32_t st = sb + (kt % H_NSTAGE) * H_STAGE_BYTES;
        #pragma unroll
        for (int s = 0; s < 3; s++) {
            uint32_t At = st + (s == 2 ? H_TILE_BYTES : 0);
            uint32_t Bt = st + (s == 1 ? 3 * H_TILE_BYTES : 2 * H_TILE_BYTES);
            #pragma unroll
            for (int ks = 0; ks < 2; ks++) {
                uint32_t a[4][4], b[2][4];
                #pragma unroll
                for (int mt = 0; mt < 4; mt++)
                    ldsm4(a[mt], At + (wm * 64 + mt * 16 + (lane & 15)) * H_ROWB
                                    + ks * 32 + (lane >> 4) * 16);
                #pragma unroll
                for (int ng = 0; ng < 2; ng++)
                    ldsm4(b[ng], Bt + (wn * 32 + ng * 16 + (lane & 15)) * H_ROWB
                                    + ks * 32 + (lane >> 4) * 16);
                #pragma unroll
                for (int mt = 0; mt < 4; mt++)
                    #pragma unroll
                    for (int nt = 0; nt < 4; nt++) {
                        uint32_t bb[2] = { b[nt >> 1][nt & 1], b[nt >> 1][(nt & 1) + 2] };
                        mma_bf16(acc[mt][nt], a[mt], bb);
                    }
            }
        }
    }

    // Epilogue: d0/d1 -> (row, col..col+1); d2/d3 -> (row+8, col..col+1)
    if (STAGE == 1) {
        #pragma unroll
        for (int mt = 0; mt < 4; mt++) {
            int row_base = m0 + wm * 64 + mt * 16 + (lane >> 2);
            #pragma unroll
            for (int nt = 0; nt < 4; nt++) {
                int col = n0 + wn * 32 + nt * 8 + (lane & 3) * 2;
                #pragma unroll
                for (int h = 0; h < 2; h++) {
                    int row = row_base + h * 8;
                    float v0 = acc[mt][nt][h * 2 + 0];
                    float v1 = acc[mt][nt][h * 2 + 1];
                    __nv_bfloat16 h0 = __float2bfloat16_rn(v0);
                    __nv_bfloat16 h1 = __float2bfloat16_rn(v1);
                    __nv_bfloat16 l0 = __float2bfloat16_rn(v0 - __bfloat162float(h0));
                    __nv_bfloat16 l1 = __float2bfloat16_rn(v1 - __bfloat162float(h1));
                    size_t off = ((size_t)z * Np + row) * Dd + col;
                    __nv_bfloat162 hh; hh.x = h0; hh.y = h1;
                    __nv_bfloat162 ll; ll.x = l0; ll.y = l1;
                    *reinterpret_cast<__nv_bfloat162*>(g_xwhi + off) = hh;
                    *reinterpret_cast<__nv_bfloat162*>(g_xwlo + off) = ll;
                }
            }
        }
    } else {
        const float bv = *bias;
        #pragma unroll
        for (int mt = 0; mt < 4; mt++) {
            int row_base = m0 + wm * 64 + mt * 16 + (lane >> 2);
            #pragma unroll
            for (int nt = 0; nt < 4; nt++) {
                int col = n0 + wn * 32 + nt * 8 + (lane & 3) * 2;
                #pragma unroll
                for (int h = 0; h < 2; h++) {
                    int row = row_base + h * 8;
                    float v0 = acc[mt][nt][h * 2 + 0] + bv;
                    float v1 = acc[mt][nt][h * 2 + 1] + bv;
                    if (row == col)     v0 = 0.0f;
                    if (row == col + 1) v1 = 0.0f;
                    *reinterpret_cast<float2*>(out + ((size_t)z * Np + row) * Np + col)
                        = make_float2(v0, v1);
                }
            }
        }
    }
#endif  // !HAS_TC
}

// ---------------------------------------------------------------------------
extern "C" void kernel_launch(void* const* d_in, const int* in_sizes, int n_in,
                              void* d_out, int out_size) {
    const float* X    = (const float*)d_in[0];   // (32, 512, 512)
    const float* W    = (const float*)d_in[1];   // (512, 512)
    const float* bias = (const float*)d_in[2];   // scalar
    float* out = (float*)d_out;                  // (32, 512, 512)

    static bool attr_done = false;
    if (!attr_done) {
        cudaFuncSetAttribute(gemm_tc<1>,   cudaFuncAttributeMaxDynamicSharedMemorySize, T_SMEM_TOTAL);
        cudaFuncSetAttribute(gemm_tc<2>,   cudaFuncAttributeMaxDynamicSharedMemorySize, T_SMEM_TOTAL);
        cudaFuncSetAttribute(gemm_hmma<1>, cudaFuncAttributeMaxDynamicSharedMemorySize, H_SMEM_TOTAL);
        cudaFuncSetAttribute(gemm_hmma<2>, cudaFuncAttributeMaxDynamicSharedMemorySize, H_SMEM_TOTAL);
        attr_done = true;
    }

    conv_x_kernel<<<(Bb * Np * Dd) / 4 / 256, 256>>>((const float4*)X);
    conv_w_kernel<<<dim3(16, 16), dim3(32, 8)>>>(W);

    dim3 grid(Np / 128, Np / 128, Bb);   // (4, 4, 32)
    // Exactly one of these pairs does work, depending on which ISA compiled.
    gemm_tc<1>  <<<grid, 256, T_SMEM_TOTAL>>>(bias, out);
    gemm_hmma<1><<<grid, 256, H_SMEM_TOTAL>>>(bias, out);
    gemm_tc<2>  <<<grid, 256, T_SMEM_TOTAL>>>(bias, out);
    gemm_hmma<2><<<grid, 256, H_SMEM_TOTAL>>>(bias, out);
}

// round 6
// speedup vs baseline: 5.1121x; 1.0711x over previous
#include <cuda_runtime.h>
#include <cuda_bf16.h>
#include <cstdint>

// tcgen05 exists only in the compute_103a pass; plain sm_103 compiles empty stubs.
#if defined(__CUDA_ARCH__) && defined(__CUDA_ARCH_FEAT_SM103_ALL)
#define HAS_TC 1
#else
#define HAS_TC 0
#endif

constexpr int Bb = 32, Np = 512, Dd = 512;

// ---------------- scratch (__device__ globals; alloc-free rule) -------------
__device__ __align__(16) __nv_bfloat16 g_xhi [(size_t)Bb * Np * Dd];
__device__ __align__(16) __nv_bfloat16 g_xlo [(size_t)Bb * Np * Dd];
__device__ __align__(16) __nv_bfloat16 g_wthi[(size_t)Dd * Dd];
__device__ __align__(16) __nv_bfloat16 g_wtlo[(size_t)Dd * Dd];
__device__ __align__(16) __nv_bfloat16 g_xwhi[(size_t)Bb * Np * Dd];
__device__ __align__(16) __nv_bfloat16 g_xwlo[(size_t)Bb * Np * Dd];

// ---------------- common helpers -------------------------------------------
__device__ __forceinline__ uint32_t smem_u32(const void* p) {
    uint32_t a;
    asm("{ .reg .u64 t; cvta.to.shared.u64 t, %1; cvt.u32.u64 %0, t; }"
        : "=r"(a) : "l"(p));
    return a;
}
__device__ __forceinline__ void cp_async16(uint32_t dst, const void* src) {
    asm volatile("cp.async.cg.shared.global [%0], [%1], 16;"
                 :: "r"(dst), "l"(src));
}
#define CP_COMMIT()  asm volatile("cp.async.commit_group;" ::: "memory")
#define CP_WAIT(n)   asm volatile("cp.async.wait_group %0;" :: "n"(n) : "memory")

// ---------------- conversion kernels ---------------------------------------
__global__ __launch_bounds__(256) void conv_x_kernel(const float4* __restrict__ X) {
    size_t i = (size_t)blockIdx.x * 256 + threadIdx.x;
    float4 v = X[i];
    union { __nv_bfloat16 b[4]; uint2 u; } H, L;
    const float* f = &v.x;
    #pragma unroll
    for (int j = 0; j < 4; j++) {
        __nv_bfloat16 h = __float2bfloat16_rn(f[j]);
        H.b[j] = h;
        L.b[j] = __float2bfloat16_rn(f[j] - __bfloat162float(h));
    }
    reinterpret_cast<uint2*>(g_xhi)[i] = H.u;
    reinterpret_cast<uint2*>(g_xlo)[i] = L.u;
}

__global__ __launch_bounds__(256) void conv_w_kernel(const float* __restrict__ W) {
    __shared__ float t[32][33];
    int tx = threadIdx.x, ty = threadIdx.y;          // 32 x 8
    int bx = blockIdx.x * 32, by = blockIdx.y * 32;  // bx: n-block, by: k-block
    #pragma unroll
    for (int r = 0; r < 4; r++)
        t[ty + r * 8][tx] = W[(size_t)(by + ty + r * 8) * Dd + bx + tx];
    __syncthreads();
    #pragma unroll
    for (int r = 0; r < 4; r++) {
        int n = bx + ty + r * 8, kk = by + tx;
        float v = t[tx][ty + r * 8];                  // = W[kk][n]
        __nv_bfloat16 h = __float2bfloat16_rn(v);
        g_wthi[(size_t)n * Dd + kk] = h;
        g_wtlo[(size_t)n * Dd + kk] = __float2bfloat16_rn(v - __bfloat162float(h));
    }
}

// ===========================================================================
// tcgen05 bf16x3 GEMM, 128(M) x 256(N) tiles, BK=64, 2-stage cp.async pipeline
// ===========================================================================
constexpr int TBM = 128, TBN = 256, TBKE = 64;
constexpr int T_KITERS = Dd / TBKE;                  // 8
constexpr int A_TILE_BYTES = TBM * TBKE * 2;         // 16384
constexpr int B_TILE_BYTES = TBN * TBKE * 2;         // 32768
constexpr int T_STAGE_BYTES = 2 * A_TILE_BYTES + 2 * B_TILE_BYTES;  // 98304
constexpr int T_OFF_MBAR  = 8;
constexpr int T_OFF_TILES = 1024;
constexpr int T_SMEM_TOTAL = T_OFF_TILES + 2 * T_STAGE_BYTES;       // 197632

#if HAS_TC
constexpr uint32_t T_IDESC =
    (1u << 4) | (1u << 7) | (1u << 10) | ((TBN / 8) << 17) | ((TBM / 16) << 24);

__device__ __forceinline__ uint32_t elect_one_pred() {
    uint32_t pred;
    asm volatile("{\n\t.reg .pred p;\n\telect.sync _|p, 0xFFFFFFFF;\n\t"
                 "selp.b32 %0, 1, 0, p;\n\t}" : "=r"(pred));
    return pred;
}
#define MBARRIER_INIT(addr, cnt) \
    asm volatile("mbarrier.init.shared.b64 [%0], %1;" :: "r"(addr), "r"(cnt) : "memory")
#define MBAR_WAIT(addr, parity) do {                                          \
    uint32_t _m = (addr), _p = (parity);                                      \
    asm volatile("{\n\t.reg .pred P1;\n\t"                                    \
        "WAIT_LOOP_%=:\n\t"                                                   \
        "mbarrier.try_wait.parity.acquire.cta.shared::cta.b64 P1, [%0], %1, 0x989680;\n\t" \
        "@P1 bra.uni WAIT_DONE_%=;\n\t"                                       \
        "bra.uni WAIT_LOOP_%=;\n\t"                                           \
        "WAIT_DONE_%=:\n\t}" :: "r"(_m), "r"(_p) : "memory");                 \
} while (0)
#define TCGEN05_ALLOC(smem_addr, n) \
    asm volatile("tcgen05.alloc.cta_group::1.sync.aligned.shared::cta.b32 [%0], %1;" \
                 :: "r"(smem_addr), "r"((uint32_t)(n)) : "memory")
#define TCGEN05_DEALLOC(tmem, n) \
    asm volatile("tcgen05.dealloc.cta_group::1.sync.aligned.b32 %0, %1;" \
                 :: "r"(tmem), "r"((uint32_t)(n)))
#define TCGEN05_RELINQ() \
    asm volatile("tcgen05.relinquish_alloc_permit.cta_group::1.sync.aligned;")
#define TCGEN05_COMMIT(mbar) \
    asm volatile("tcgen05.commit.cta_group::1.mbarrier::arrive::one.shared::cluster.b64 [%0];" \
                 :: "r"(mbar) : "memory")
#define TCGEN05_FENCE_AFTER() \
    asm volatile("tcgen05.fence::after_thread_sync;" ::: "memory")
#define TCGEN05_FENCE_BEFORE() \
    asm volatile("tcgen05.fence::before_thread_sync;" ::: "memory")
#define TCGEN05_WAIT_LD() \
    asm volatile("tcgen05.wait::ld.sync.aligned;" ::: "memory")
#define FENCE_ASYNC_SHARED() \
    asm volatile("fence.proxy.async.shared::cta;" ::: "memory")
#define MMA_BF16_SS(dtmem, adesc, bdesc, idesc, enable) do {                  \
    uint32_t _e = (enable); uint32_t _z = 0;                                  \
    asm volatile("{\n\t.reg .pred p;\n\tsetp.ne.u32 p, %5, 0;\n\t"            \
        "tcgen05.mma.cta_group::1.kind::f16 [%0], %1, %2, %3, {%4,%4,%4,%4}, p;\n\t}" \
        :: "r"(dtmem), "l"(adesc), "l"(bdesc), "r"(idesc), "r"(_z), "r"(_e)   \
        : "memory");                                                          \
} while (0)
#define TCGEN05_LD_X32(r, tmem_addr) \
    asm volatile( \
        "tcgen05.ld.sync.aligned.32x32b.x32.b32 " \
        "{%0, %1, %2, %3, %4, %5, %6, %7, %8, %9, %10, %11, %12, %13, %14, %15, " \
        " %16, %17, %18, %19, %20, %21, %22, %23, %24, %25, %26, %27, %28, %29, %30, %31}, [%32];" \
        : "=r"((r)[0]),  "=r"((r)[1]),  "=r"((r)[2]),  "=r"((r)[3]),  \
          "=r"((r)[4]),  "=r"((r)[5]),  "=r"((r)[6]),  "=r"((r)[7]),  \
          "=r"((r)[8]),  "=r"((r)[9]),  "=r"((r)[10]), "=r"((r)[11]), \
          "=r"((r)[12]), "=r"((r)[13]), "=r"((r)[14]), "=r"((r)[15]), \
          "=r"((r)[16]), "=r"((r)[17]), "=r"((r)[18]), "=r"((r)[19]), \
          "=r"((r)[20]), "=r"((r)[21]), "=r"((r)[22]), "=r"((r)[23]), \
          "=r"((r)[24]), "=r"((r)[25]), "=r"((r)[26]), "=r"((r)[27]), \
          "=r"((r)[28]), "=r"((r)[29]), "=r"((r)[30]), "=r"((r)[31]) \
        : "r"(tmem_addr))

static constexpr uint64_t DESC_BASE_SW128 =
    (uint64_t(2) << 61) | (uint64_t(1) << 46) | (uint64_t(64) << 32) | (uint64_t(1) << 16);
__device__ __forceinline__ uint64_t make_desc(uint32_t addr) {
    return DESC_BASE_SW128 | ((uint64_t)(addr >> 4) & 0x3FFF);
}
#endif  // HAS_TC

template <int STAGE>
__global__ void __launch_bounds__(256, 1) gemm_tc(const float* __restrict__ bias,
                                                  float* __restrict__ out) {
#if HAS_TC
    extern __shared__ char smem[];
    uint32_t sb = smem_u32(smem);
    const int tid = threadIdx.x;
    const int wid = tid >> 5, lid = tid & 31;
    const int z  = blockIdx.z;
    const int m0 = blockIdx.y * TBM, n0 = blockIdx.x * TBN;

    const __nv_bfloat16 *Ahi, *Alo, *Bhi, *Blo;
    if (STAGE == 1) {
        Ahi = g_xhi  + (size_t)z * Np * Dd;  Alo = g_xlo  + (size_t)z * Np * Dd;
        Bhi = g_wthi;                        Blo = g_wtlo;
    } else {
        Ahi = g_xwhi + (size_t)z * Np * Dd;  Alo = g_xwlo + (size_t)z * Np * Dd;
        Bhi = g_xhi  + (size_t)z * Np * Dd;  Blo = g_xlo  + (size_t)z * Np * Dd;
    }

    if (tid == 0) {
        MBARRIER_INIT(sb + T_OFF_MBAR + 0, 1);
        MBARRIER_INIT(sb + T_OFF_MBAR + 8, 1);
    }
    if (wid == 0) TCGEN05_ALLOC(sb, 256);
    __syncthreads();
    uint32_t tmem;
    asm volatile("ld.shared.b32 %0, [%1];" : "=r"(tmem) : "r"(sb));
    if (wid == 0) TCGEN05_RELINQ();

    // SW128-swizzled K-major tile fill. rows128: 4 chunks/thread; rows256: 8.
    auto load_tile = [&](uint32_t tile, const __nv_bfloat16* src, int row0, int k0,
                         int nchunk) {
        const char* gp = reinterpret_cast<const char*>(src);
        for (int i = 0; i < nchunk; i++) {
            int chunk = tid + i * 256;
            int row = chunk >> 3;
            int c   = (chunk & 7) * 16;
            cp_async16(tile + row * 128 + (c ^ ((row & 7) << 4)),
                       gp + (size_t)(row0 + row) * (Dd * 2) + k0 * 2 + c);
        }
    };
    auto load_iter = [&](int it) {
        uint32_t stg = sb + T_OFF_TILES + (it & 1) * T_STAGE_BYTES;
        int k0 = it * TBKE;
        load_tile(stg,                    Ahi, m0, k0, 4);
        load_tile(stg + A_TILE_BYTES,     Alo, m0, k0, 4);
        load_tile(stg + 2 * A_TILE_BYTES, Bhi, n0, k0, 8);
        load_tile(stg + 2 * A_TILE_BYTES + B_TILE_BYTES, Blo, n0, k0, 8);
        CP_COMMIT();
    };
    load_iter(0);
    load_iter(1);

    for (int k = 0; k < T_KITERS; k++) {
        if (k == T_KITERS - 1) { CP_WAIT(0); } else { CP_WAIT(1); }
        FENCE_ASYNC_SHARED();
        __syncthreads();

        if (wid == 0) {
            uint32_t stg = sb + T_OFF_TILES + (k & 1) * T_STAGE_BYTES;
            uint64_t dAh = make_desc(stg);
            uint64_t dAl = make_desc(stg + A_TILE_BYTES);
            uint64_t dBh = make_desc(stg + 2 * A_TILE_BYTES);
            uint64_t dBl = make_desc(stg + 2 * A_TILE_BYTES + B_TILE_BYTES);
            if (elect_one_pred()) {
                #pragma unroll
                for (int s = 0; s < 4; s++) {             // K=16 per MMA
                    uint64_t o = (uint64_t)(s * 2);
                    MMA_BF16_SS(tmem, dAh + o, dBh + o, T_IDESC, (k == 0 && s == 0) ? 0u : 1u);
                    MMA_BF16_SS(tmem, dAh + o, dBl + o, T_IDESC, 1u);
                    MMA_BF16_SS(tmem, dAl + o, dBh + o, T_IDESC, 1u);
                }
                TCGEN05_COMMIT(sb + T_OFF_MBAR + (k & 1) * 8);
            }
        }

        if (k + 2 < T_KITERS) {
            // stage (k&1) is reused by iter k+2: wait for MMA k to drain it
            MBAR_WAIT(sb + T_OFF_MBAR + (k & 1) * 8, (k >> 1) & 1);
            load_iter(k + 2);
        }
    }

    MBAR_WAIT(sb + T_OFF_MBAR + ((T_KITERS - 1) & 1) * 8, ((T_KITERS - 1) >> 1) & 1);
    TCGEN05_FENCE_AFTER();

    // Epilogue: 8 warps. Warps 0-3 -> cols [0,128), warps 4-7 -> cols [128,256).
    {
        const int half = wid >> 2;
        const int gi   = m0 + (wid & 3) * 32 + lid;
        const int cbase = half * 128;
        if (STAGE == 1) {
            size_t base = ((size_t)z * Np + gi) * Dd + n0 + cbase;
            #pragma unroll
            for (int c0 = 0; c0 < 128; c0 += 32) {
                uint32_t r[32];
                TCGEN05_LD_X32(r, tmem + cbase + c0);
                TCGEN05_WAIT_LD();
                __align__(16) __nv_bfloat16 hs[32], ls[32];
                #pragma unroll
                for (int c = 0; c < 32; c++) {
                    float v = __uint_as_float(r[c]);
                    __nv_bfloat16 h = __float2bfloat16_rn(v);
                    hs[c] = h;
                    ls[c] = __float2bfloat16_rn(v - __bfloat162float(h));
                }
                uint4* dh = reinterpret_cast<uint4*>(g_xwhi + base + c0);
                uint4* dl = reinterpret_cast<uint4*>(g_xwlo + base + c0);
                const uint4* sh = reinterpret_cast<const uint4*>(hs);
                const uint4* sl = reinterpret_cast<const uint4*>(ls);
                #pragma unroll
                for (int q = 0; q < 4; q++) { dh[q] = sh[q]; dl[q] = sl[q]; }
            }
        } else {
            const float bv = *bias;
            size_t base = ((size_t)z * Np + gi) * Np + n0 + cbase;
            #pragma unroll
            for (int c0 = 0; c0 < 128; c0 += 32) {
                uint32_t r[32];
                TCGEN05_LD_X32(r, tmem + cbase + c0);
                TCGEN05_WAIT_LD();
                __align__(16) float vs[32];
                #pragma unroll
                for (int c = 0; c < 32; c++) {
                    int gj = n0 + cbase + c0 + c;
                    float v = __uint_as_float(r[c]) + bv;
                    vs[c] = (gi == gj) ? 0.0f : v;
                }
                float4* d = reinterpret_cast<float4*>(out + base + c0);
                const float4* s = reinterpret_cast<const float4*>(vs);
                #pragma unroll
                for (int q = 0; q < 8; q++) d[q] = s[q];
            }
        }
        TCGEN05_FENCE_BEFORE();
    }
    __syncthreads();
    if (wid == 0) TCGEN05_DEALLOC(tmem, 256);
#endif  // HAS_TC
}

// ---------------------------------------------------------------------------
extern "C" void kernel_launch(void* const* d_in, const int* in_sizes, int n_in,
                              void* d_out, int out_size) {
    const float* X    = (const float*)d_in[0];   // (32, 512, 512)
    const float* W    = (const float*)d_in[1];   // (512, 512)
    const float* bias = (const float*)d_in[2];   // scalar
    float* out = (float*)d_out;                  // (32, 512, 512)

    // Idempotent; no static guards (harness rule).
    cudaFuncSetAttribute(gemm_tc<1>, cudaFuncAttributeMaxDynamicSharedMemorySize, T_SMEM_TOTAL);
    cudaFuncSetAttribute(gemm_tc<2>, cudaFuncAttributeMaxDynamicSharedMemorySize, T_SMEM_TOTAL);

    conv_x_kernel<<<(Bb * Np * Dd) / 4 / 256, 256>>>((const float4*)X);
    conv_w_kernel<<<dim3(16, 16), dim3(32, 8)>>>(W);

    dim3 grid(Np / TBN, Np / TBM, Bb);   // (2, 4, 32) = 256 CTAs
    gemm_tc<1><<<grid, 256, T_SMEM_TOTAL>>>(bias, out);
    gemm_tc<2><<<grid, 256, T_SMEM_TOTAL>>>(bias, out);
}

// round 7
// speedup vs baseline: 5.2543x; 1.0278x over previous
#include <cuda_runtime.h>
#include <cuda_bf16.h>
#include <cstdint>

// tcgen05 exists only in the compute_103a pass; plain sm_103 compiles empty stubs.
#if defined(__CUDA_ARCH__) && defined(__CUDA_ARCH_FEAT_SM103_ALL)
#define HAS_TC 1
#else
#define HAS_TC 0
#endif

constexpr int Bb = 32, Np = 512, Dd = 512;

// ---------------- scratch (__device__ globals; alloc-free rule) -------------
__device__ __align__(16) __nv_bfloat16 g_xhi [(size_t)Bb * Np * Dd];
__device__ __align__(16) __nv_bfloat16 g_xlo [(size_t)Bb * Np * Dd];
__device__ __align__(16) __nv_bfloat16 g_wthi[(size_t)Dd * Dd];
__device__ __align__(16) __nv_bfloat16 g_wtlo[(size_t)Dd * Dd];
__device__ __align__(16) __nv_bfloat16 g_xwhi[(size_t)Bb * Np * Dd];
__device__ __align__(16) __nv_bfloat16 g_xwlo[(size_t)Bb * Np * Dd];

// ---------------- common helpers -------------------------------------------
__device__ __forceinline__ uint32_t smem_u32(const void* p) {
    uint32_t a;
    asm("{ .reg .u64 t; cvta.to.shared.u64 t, %1; cvt.u32.u64 %0, t; }"
        : "=r"(a) : "l"(p));
    return a;
}
__device__ __forceinline__ void cp_async16(uint32_t dst, const void* src) {
    asm volatile("cp.async.cg.shared.global [%0], [%1], 16;"
                 :: "r"(dst), "l"(src));
}
#define CP_COMMIT()  asm volatile("cp.async.commit_group;" ::: "memory")
#define CP_WAIT(n)   asm volatile("cp.async.wait_group %0;" :: "n"(n) : "memory")

// ---------------- conversion kernels ---------------------------------------
__global__ __launch_bounds__(256) void conv_x_kernel(const float4* __restrict__ X) {
    size_t i = (size_t)blockIdx.x * 256 + threadIdx.x;
    float4 v = X[i];
    union { __nv_bfloat16 b[4]; uint2 u; } H, L;
    const float* f = &v.x;
    #pragma unroll
    for (int j = 0; j < 4; j++) {
        __nv_bfloat16 h = __float2bfloat16_rn(f[j]);
        H.b[j] = h;
        L.b[j] = __float2bfloat16_rn(f[j] - __bfloat162float(h));
    }
    reinterpret_cast<uint2*>(g_xhi)[i] = H.u;
    reinterpret_cast<uint2*>(g_xlo)[i] = L.u;
}

__global__ __launch_bounds__(256) void conv_w_kernel(const float* __restrict__ W) {
    __shared__ float t[32][33];
    int tx = threadIdx.x, ty = threadIdx.y;          // 32 x 8
    int bx = blockIdx.x * 32, by = blockIdx.y * 32;  // bx: n-block, by: k-block
    #pragma unroll
    for (int r = 0; r < 4; r++)
        t[ty + r * 8][tx] = W[(size_t)(by + ty + r * 8) * Dd + bx + tx];
    __syncthreads();
    #pragma unroll
    for (int r = 0; r < 4; r++) {
        int n = bx + ty + r * 8, kk = by + tx;
        float v = t[tx][ty + r * 8];                  // = W[kk][n]
        __nv_bfloat16 h = __float2bfloat16_rn(v);
        g_wthi[(size_t)n * Dd + kk] = h;
        g_wtlo[(size_t)n * Dd + kk] = __float2bfloat16_rn(v - __bfloat162float(h));
    }
}

// ===========================================================================
// tcgen05 bf16x3 GEMM, 128(M) x 256(N), K pipelined in 16 half-stages of K=32
// SMEM: 2 full K=64 SW128 stages (96 KB each); commit-group = half-stage 48 KB.
// Loads run 3 half-iterations ahead -> DRAM/L2 latency hidden.
// ===========================================================================
constexpr int TBM = 128, TBN = 256;
constexpr int NHALF = 16;                            // 512 / 32
constexpr int A_TILE_BYTES = TBM * 64 * 2;           // 16384
constexpr int B_TILE_BYTES = TBN * 64 * 2;           // 32768
constexpr int T_STAGE_BYTES = 2 * A_TILE_BYTES + 2 * B_TILE_BYTES;  // 98304
constexpr int T_OFF_MBAR  = 8;                       // 4 mbarriers
constexpr int T_OFF_TILES = 1024;
constexpr int T_SMEM_TOTAL = T_OFF_TILES + 2 * T_STAGE_BYTES;       // 197632

#if HAS_TC
constexpr uint32_t T_IDESC =
    (1u << 4) | (1u << 7) | (1u << 10) | ((TBN / 8) << 17) | ((TBM / 16) << 24);

__device__ __forceinline__ uint32_t elect_one_pred() {
    uint32_t pred;
    asm volatile("{\n\t.reg .pred p;\n\telect.sync _|p, 0xFFFFFFFF;\n\t"
                 "selp.b32 %0, 1, 0, p;\n\t}" : "=r"(pred));
    return pred;
}
#define MBARRIER_INIT(addr, cnt) \
    asm volatile("mbarrier.init.shared.b64 [%0], %1;" :: "r"(addr), "r"(cnt) : "memory")
#define MBAR_WAIT(addr, parity) do {                                          \
    uint32_t _m = (addr), _p = (parity);                                      \
    asm volatile("{\n\t.reg .pred P1;\n\t"                                    \
        "WAIT_LOOP_%=:\n\t"                                                   \
        "mbarrier.try_wait.parity.acquire.cta.shared::cta.b64 P1, [%0], %1, 0x989680;\n\t" \
        "@P1 bra.uni WAIT_DONE_%=;\n\t"                                       \
        "bra.uni WAIT_LOOP_%=;\n\t"                                           \
        "WAIT_DONE_%=:\n\t}" :: "r"(_m), "r"(_p) : "memory");                 \
} while (0)
#define TCGEN05_ALLOC(smem_addr, n) \
    asm volatile("tcgen05.alloc.cta_group::1.sync.aligned.shared::cta.b32 [%0], %1;" \
                 :: "r"(smem_addr), "r"((uint32_t)(n)) : "memory")
#define TCGEN05_DEALLOC(tmem, n) \
    asm volatile("tcgen05.dealloc.cta_group::1.sync.aligned.b32 %0, %1;" \
                 :: "r"(tmem), "r"((uint32_t)(n)))
#define TCGEN05_RELINQ() \
    asm volatile("tcgen05.relinquish_alloc_permit.cta_group::1.sync.aligned;")
#define TCGEN05_COMMIT(mbar) \
    asm volatile("tcgen05.commit.cta_group::1.mbarrier::arrive::one.shared::cluster.b64 [%0];" \
                 :: "r"(mbar) : "memory")
#define TCGEN05_FENCE_AFTER() \
    asm volatile("tcgen05.fence::after_thread_sync;" ::: "memory")
#define TCGEN05_FENCE_BEFORE() \
    asm volatile("tcgen05.fence::before_thread_sync;" ::: "memory")
#define TCGEN05_WAIT_LD() \
    asm volatile("tcgen05.wait::ld.sync.aligned;" ::: "memory")
#define FENCE_ASYNC_SHARED() \
    asm volatile("fence.proxy.async.shared::cta;" ::: "memory")
#define MMA_BF16_SS(dtmem, adesc, bdesc, idesc, enable) do {                  \
    uint32_t _e = (enable); uint32_t _z = 0;                                  \
    asm volatile("{\n\t.reg .pred p;\n\tsetp.ne.u32 p, %5, 0;\n\t"            \
        "tcgen05.mma.cta_group::1.kind::f16 [%0], %1, %2, %3, {%4,%4,%4,%4}, p;\n\t}" \
        :: "r"(dtmem), "l"(adesc), "l"(bdesc), "r"(idesc), "r"(_z), "r"(_e)   \
        : "memory");                                                          \
} while (0)
#define TCGEN05_LD_X32(r, tmem_addr) \
    asm volatile( \
        "tcgen05.ld.sync.aligned.32x32b.x32.b32 " \
        "{%0, %1, %2, %3, %4, %5, %6, %7, %8, %9, %10, %11, %12, %13, %14, %15, " \
        " %16, %17, %18, %19, %20, %21, %22, %23, %24, %25, %26, %27, %28, %29, %30, %31}, [%32];" \
        : "=r"((r)[0]),  "=r"((r)[1]),  "=r"((r)[2]),  "=r"((r)[3]),  \
          "=r"((r)[4]),  "=r"((r)[5]),  "=r"((r)[6]),  "=r"((r)[7]),  \
          "=r"((r)[8]),  "=r"((r)[9]),  "=r"((r)[10]), "=r"((r)[11]), \
          "=r"((r)[12]), "=r"((r)[13]), "=r"((r)[14]), "=r"((r)[15]), \
          "=r"((r)[16]), "=r"((r)[17]), "=r"((r)[18]), "=r"((r)[19]), \
          "=r"((r)[20]), "=r"((r)[21]), "=r"((r)[22]), "=r"((r)[23]), \
          "=r"((r)[24]), "=r"((r)[25]), "=r"((r)[26]), "=r"((r)[27]), \
          "=r"((r)[28]), "=r"((r)[29]), "=r"((r)[30]), "=r"((r)[31]) \
        : "r"(tmem_addr))

static constexpr uint64_t DESC_BASE_SW128 =
    (uint64_t(2) << 61) | (uint64_t(1) << 46) | (uint64_t(64) << 32) | (uint64_t(1) << 16);
__device__ __forceinline__ uint64_t make_desc(uint32_t addr) {
    return DESC_BASE_SW128 | ((uint64_t)(addr >> 4) & 0x3FFF);
}
#endif  // HAS_TC

template <int STAGE>
__global__ void __launch_bounds__(256, 1) gemm_tc(const float* __restrict__ bias,
                                                  float* __restrict__ out) {
#if HAS_TC
    extern __shared__ char smem[];
    uint32_t sb = smem_u32(smem);
    const int tid = threadIdx.x;
    const int wid = tid >> 5, lid = tid & 31;
    const int z  = blockIdx.z;
    const int m0 = blockIdx.y * TBM, n0 = blockIdx.x * TBN;

    const __nv_bfloat16 *Ahi, *Alo, *Bhi, *Blo;
    if (STAGE == 1) {
        Ahi = g_xhi  + (size_t)z * Np * Dd;  Alo = g_xlo  + (size_t)z * Np * Dd;
        Bhi = g_wthi;                        Blo = g_wtlo;
    } else {
        Ahi = g_xwhi + (size_t)z * Np * Dd;  Alo = g_xwlo + (size_t)z * Np * Dd;
        Bhi = g_xhi  + (size_t)z * Np * Dd;  Blo = g_xlo  + (size_t)z * Np * Dd;
    }

    if (tid == 0) {
        #pragma unroll
        for (int s = 0; s < 4; s++) MBARRIER_INIT(sb + T_OFF_MBAR + s * 8, 1);
    }
    if (wid == 0) TCGEN05_ALLOC(sb, 256);
    __syncthreads();
    uint32_t tmem;
    asm volatile("ld.shared.b32 %0, [%1];" : "=r"(tmem) : "r"(sb));
    if (wid == 0) TCGEN05_RELINQ();

    // Load the K=32 half `h` of all four operand tiles (one commit group, 48KB).
    // Stage = (h>>1)&1, local column offset = (h&1)*64 bytes, SW128 swizzle.
    auto load_half = [&](int h) {
        uint32_t stg = sb + T_OFF_TILES + ((h >> 1) & 1) * T_STAGE_BYTES;
        const int coloff = (h & 1) * 64;        // bytes within 128B row
        const size_t k0b = (size_t)h * 64;      // global K offset in bytes
        // A tiles: 128 rows x 64B = 512 chunks -> 2/thread each
        {
            const char* gh = reinterpret_cast<const char*>(Ahi) + (size_t)m0 * 1024 + k0b;
            const char* gl = reinterpret_cast<const char*>(Alo) + (size_t)m0 * 1024 + k0b;
            #pragma unroll
            for (int i = 0; i < 2; i++) {
                int chunk = tid + i * 256;
                int row = chunk >> 2;
                int c   = (chunk & 3) * 16;
                uint32_t soff = row * 128 + ((coloff + c) ^ ((row & 7) << 4));
                size_t goff = (size_t)row * 1024 + c;
                cp_async16(stg + soff,                gh + goff);
                cp_async16(stg + A_TILE_BYTES + soff, gl + goff);
            }
        }
        // B tiles: 256 rows x 64B = 1024 chunks -> 4/thread each
        {
            uint32_t bstg = stg + 2 * A_TILE_BYTES;
            const char* gh = reinterpret_cast<const char*>(Bhi) + (size_t)n0 * 1024 + k0b;
            const char* gl = reinterpret_cast<const char*>(Blo) + (size_t)n0 * 1024 + k0b;
            #pragma unroll
            for (int i = 0; i < 4; i++) {
                int chunk = tid + i * 256;
                int row = chunk >> 2;
                int c   = (chunk & 3) * 16;
                uint32_t soff = row * 128 + ((coloff + c) ^ ((row & 7) << 4));
                size_t goff = (size_t)row * 1024 + c;
                cp_async16(bstg + soff,                gh + goff);
                cp_async16(bstg + B_TILE_BYTES + soff, gl + goff);
            }
        }
        CP_COMMIT();
    };

    load_half(0);
    load_half(1);
    load_half(2);

    for (int h = 0; h < NHALF; h++) {
        // This thread's group h done when <= min(2, 15-h) groups outstanding.
        if (h <= 13)      { CP_WAIT(2); }
        else if (h == 14) { CP_WAIT(1); }
        else              { CP_WAIT(0); }
        FENCE_ASYNC_SHARED();
        __syncthreads();   // all threads' copies for half h complete

        if (wid == 0) {
            uint32_t stg = sb + T_OFF_TILES + ((h >> 1) & 1) * T_STAGE_BYTES;
            uint64_t dAh = make_desc(stg);
            uint64_t dAl = make_desc(stg + A_TILE_BYTES);
            uint64_t dBh = make_desc(stg + 2 * A_TILE_BYTES);
            uint64_t dBl = make_desc(stg + 2 * A_TILE_BYTES + B_TILE_BYTES);
            if (elect_one_pred()) {
                const uint64_t hoff = (uint64_t)((h & 1) * 4);
                #pragma unroll
                for (int s = 0; s < 2; s++) {             // two K=16 steps
                    uint64_t o = hoff + (uint64_t)(s * 2);
                    MMA_BF16_SS(tmem, dAh + o, dBh + o, T_IDESC, (h == 0 && s == 0) ? 0u : 1u);
                    MMA_BF16_SS(tmem, dAh + o, dBl + o, T_IDESC, 1u);
                    MMA_BF16_SS(tmem, dAl + o, dBh + o, T_IDESC, 1u);
                }
                TCGEN05_COMMIT(sb + T_OFF_MBAR + (h & 3) * 8);
            }
        }

        if (h + 3 < NHALF) {
            // load(h+3) overwrites half (h-1)'s buffer: wait its MMAs drained
            if (h >= 1)
                MBAR_WAIT(sb + T_OFF_MBAR + ((h - 1) & 3) * 8, ((h - 1) >> 2) & 1);
            load_half(h + 3);
        }
    }

    MBAR_WAIT(sb + T_OFF_MBAR + 3 * 8, 1);   // half 15 = 4th completion on mbar[3]
    TCGEN05_FENCE_AFTER();

    // Epilogue: 8 warps. Warps 0-3 -> cols [0,128), warps 4-7 -> cols [128,256).
    {
        const int half = wid >> 2;
        const int gi   = m0 + (wid & 3) * 32 + lid;
        const int cbase = half * 128;
        if (STAGE == 1) {
            size_t base = ((size_t)z * Np + gi) * Dd + n0 + cbase;
            #pragma unroll
            for (int c0 = 0; c0 < 128; c0 += 32) {
                uint32_t r[32];
                TCGEN05_LD_X32(r, tmem + cbase + c0);
                TCGEN05_WAIT_LD();
                __align__(16) __nv_bfloat16 hs[32], ls[32];
                #pragma unroll
                for (int c = 0; c < 32; c++) {
                    float v = __uint_as_float(r[c]);
                    __nv_bfloat16 hh = __float2bfloat16_rn(v);
                    hs[c] = hh;
                    ls[c] = __float2bfloat16_rn(v - __bfloat162float(hh));
                }
                uint4* dh = reinterpret_cast<uint4*>(g_xwhi + base + c0);
                uint4* dl = reinterpret_cast<uint4*>(g_xwlo + base + c0);
                const uint4* sh = reinterpret_cast<const uint4*>(hs);
                const uint4* sl = reinterpret_cast<const uint4*>(ls);
                #pragma unroll
                for (int q = 0; q < 4; q++) { dh[q] = sh[q]; dl[q] = sl[q]; }
            }
        } else {
            const float bv = *bias;
            size_t base = ((size_t)z * Np + gi) * Np + n0 + cbase;
            #pragma unroll
            for (int c0 = 0; c0 < 128; c0 += 32) {
                uint32_t r[32];
                TCGEN05_LD_X32(r, tmem + cbase + c0);
                TCGEN05_WAIT_LD();
                __align__(16) float vs[32];
                #pragma unroll
                for (int c = 0; c < 32; c++) {
                    int gj = n0 + cbase + c0 + c;
                    float v = __uint_as_float(r[c]) + bv;
                    vs[c] = (gi == gj) ? 0.0f : v;
                }
                float4* d = reinterpret_cast<float4*>(out + base + c0);
                const float4* s = reinterpret_cast<const float4*>(vs);
                #pragma unroll
                for (int q = 0; q < 8; q++) d[q] = s[q];
            }
        }
        TCGEN05_FENCE_BEFORE();
    }
    __syncthreads();
    if (wid == 0) TCGEN05_DEALLOC(tmem, 256);
#endif  // HAS_TC
}

// ---------------------------------------------------------------------------
extern "C" void kernel_launch(void* const* d_in, const int* in_sizes, int n_in,
                              void* d_out, int out_size) {
    const float* X    = (const float*)d_in[0];   // (32, 512, 512)
    const float* W    = (const float*)d_in[1];   // (512, 512)
    const float* bias = (const float*)d_in[2];   // scalar
    float* out = (float*)d_out;                  // (32, 512, 512)

    cudaFuncSetAttribute(gemm_tc<1>, cudaFuncAttributeMaxDynamicSharedMemorySize, T_SMEM_TOTAL);
    cudaFuncSetAttribute(gemm_tc<2>, cudaFuncAttributeMaxDynamicSharedMemorySize, T_SMEM_TOTAL);

    conv_x_kernel<<<(Bb * Np * Dd) / 4 / 256, 256>>>((const float4*)X);
    conv_w_kernel<<<dim3(16, 16), dim3(32, 8)>>>(W);

    dim3 grid(Np / TBN, Np / TBM, Bb);   // (2, 4, 32) = 256 CTAs
    gemm_tc<1><<<grid, 256, T_SMEM_TOTAL>>>(bias, out);
    gemm_tc<2><<<grid, 256, T_SMEM_TOTAL>>>(bias, out);
}